// round 1
// baseline (speedup 1.0000x reference)
#include <cuda_runtime.h>
#include <cstdint>
#include <cstddef>

// Scaled_Dot_Product_Attention_neg : B=16, LQ=LK=2048, D=128 (fp32)
//   s   = -(Q K^T) * scale
//   p   = softmax(s)            (row-wise over k)   -> attention = -p
//   t   = -p * kg_sim
//   beta= softmax(t)
//   out = beta @ V
//
// Two-pass streaming formulation per (batch, q-tile):
//   pass 1: Z1[q] = sum_k exp(s)        (no max needed: s ~ N(0,1))
//   pass 2: p = exp(s)/Z1 ; w = exp(-p*g) ; Z2 += w ; acc += w*V ; out = acc/Z2
//           (t = -p*g in (-1,0] -> exp stable without max)
//
// tf32 mma.sync (m16n8k8) with explicit cvt.rna.tf32 rounding on all operands
// (truncation bias of ~1e-3 on W*V would breach the 1e-3 rel-err threshold).

#define DEV __device__ __forceinline__

static constexpr int Bn  = 16;
static constexpr int LQ  = 2048;
static constexpr int LK  = 2048;
static constexpr int Dm  = 128;

static constexpr int TQ  = 64;
static constexpr int TK  = 64;
static constexpr int NKT = LK / TK;        // 32 k-tiles
static constexpr int THREADS = 256;        // 8 warps: 4 along M x 2 along N/D

static constexpr int KSTRIDE = Dm + 4;     // 132 floats per K/V row (pad)
static constexpr int GSTRIDE = TK + 4;     // 68 floats per G/W row (pad)

// shared memory layout (in floats)
static constexpr int SZ_KBUF = TK * KSTRIDE;            // 8448
static constexpr int SZ_GBUF = TQ * GSTRIDE;            // 4352
static constexpr int OFF_K   = 0;                       // [2][TK][KSTRIDE]
static constexpr int OFF_V   = OFF_K + 2 * SZ_KBUF;     // [2][TK][KSTRIDE]
static constexpr int OFF_G   = OFF_V + 2 * SZ_KBUF;     // [2][TQ][GSTRIDE]
static constexpr int OFF_W   = OFF_G + 2 * SZ_GBUF;     // [TQ][GSTRIDE]
static constexpr int OFF_Z1  = OFF_W + SZ_GBUF;
static constexpr int OFF_Z2  = OFF_Z1 + TQ;
static constexpr int SMEM_FLOATS = OFF_Z2 + TQ;
static constexpr int SMEM_BYTES  = SMEM_FLOATS * 4;     // 187,904 B

// ---------------------------------------------------------------- helpers

DEV uint32_t f2tf(float f) {
    uint32_t r;
    asm("cvt.rna.tf32.f32 %0, %1;" : "=r"(r) : "f"(f));
    return r;
}

DEV void mma8(float* d, const uint32_t* a, const uint32_t* b) {
    asm volatile(
        "mma.sync.aligned.m16n8k8.row.col.f32.tf32.tf32.f32 "
        "{%0,%1,%2,%3}, {%4,%5,%6,%7}, {%8,%9}, {%0,%1,%2,%3};\n"
        : "+f"(d[0]), "+f"(d[1]), "+f"(d[2]), "+f"(d[3])
        : "r"(a[0]), "r"(a[1]), "r"(a[2]), "r"(a[3]),
          "r"(b[0]), "r"(b[1]));
}

DEV void cpa16(float* smem_dst, const float* gmem_src) {
    uint32_t sa = (uint32_t)__cvta_generic_to_shared(smem_dst);
    asm volatile("cp.async.cg.shared.global [%0], [%1], 16;\n"
                 :: "r"(sa), "l"(gmem_src));
}
DEV void cp_commit() { asm volatile("cp.async.commit_group;\n"); }
template <int N> DEV void cp_wait() {
    asm volatile("cp.async.wait_group %0;\n" :: "n"(N));
}

// K/V tile: TK(=64) rows x 128 floats, 2048 float4 / 256 threads = 8 each
DEV void load_KV(float* dst, const float* src_tile, int tid) {
#pragma unroll
    for (int i = 0; i < 8; i++) {
        int idx = i * 256 + tid;
        int row = idx >> 5;
        int c4  = idx & 31;
        cpa16(dst + row * KSTRIDE + c4 * 4,
              src_tile + (size_t)row * Dm + c4 * 4);
    }
}

// G tile: TQ(=64) rows x 64 floats, 1024 float4 / 256 threads = 4 each
DEV void load_G(float* dst, const float* src_tile, int tid) {
#pragma unroll
    for (int i = 0; i < 4; i++) {
        int idx = i * 256 + tid;
        int row = idx >> 4;
        int c4  = idx & 15;
        cpa16(dst + row * GSTRIDE + c4 * 4,
              src_tile + (size_t)row * LK + c4 * 4);
    }
}

// S = Q * K^T for this warp's 16-row x 32-col chunk. qa holds tf32 Q frags.
DEV void computeS(float s[4][4], const float* Ks,
                  const uint32_t (&qa)[16][4], int nw, int g, int t) {
#pragma unroll
    for (int j = 0; j < 4; j++)
#pragma unroll
        for (int r = 0; r < 4; r++) s[j][r] = 0.f;

#pragma unroll
    for (int kk = 0; kk < 16; kk++) {
#pragma unroll
        for (int j = 0; j < 4; j++) {
            const float* kp = Ks + (nw * 32 + j * 8 + g) * KSTRIDE + kk * 8 + t;
            uint32_t bb[2] = { f2tf(kp[0]), f2tf(kp[4]) };
            mma8(s[j], qa[kk], bb);
        }
    }
}

// ---------------------------------------------------------------- kernel

__global__ void __launch_bounds__(THREADS, 1)
attn_neg_kernel(const float* __restrict__ Q, const float* __restrict__ K,
                const float* __restrict__ V, const float* __restrict__ scale_p,
                const float* __restrict__ G, float* __restrict__ out) {
    extern __shared__ float sm[];
    const int tid  = threadIdx.x;
    const int wid  = tid >> 5;
    const int lane = tid & 31;
    const int mw   = wid & 3;      // warp row-band  (0..3) -> rows 16*mw
    const int nw   = wid >> 2;     // warp col-half  (0..1)
    const int g    = lane >> 2;    // mma groupID
    const int t    = lane & 3;     // mma threadID_in_group

    const int b  = blockIdx.y;
    const int q0 = blockIdx.x * TQ;
    const float sc = *scale_p;

    const float* Qg  = Q + ((size_t)b * LQ + q0) * Dm;
    const float* Kgb = K + (size_t)b * LK * Dm;
    const float* Vgb = V + (size_t)b * LK * Dm;
    const float* Gg0 = G + ((size_t)b * LQ + q0) * (size_t)LK;

    float* KsBuf = sm + OFF_K;
    float* VsBuf = sm + OFF_V;
    float* GsBuf = sm + OFF_G;
    float* Ws    = sm + OFF_W;
    float* Z1    = sm + OFF_Z1;
    float* Z2    = sm + OFF_Z2;

    // ---- stage Q into (currently unused) V buffer, zero Z arrays ----
    {
        float* Qs = VsBuf;
#pragma unroll
        for (int i = 0; i < 8; i++) {
            int idx = i * 256 + tid;
            int row = idx >> 5;
            int c4  = idx & 31;
            float4 v = *(const float4*)(Qg + (size_t)row * Dm + c4 * 4);
            *(float4*)(Qs + row * KSTRIDE + c4 * 4) = v;
        }
        if (tid < TQ) { Z1[tid] = 0.f; Z2[tid] = 0.f; }
    }
    __syncthreads();

    const int r0 = mw * 16;

    // ---- preload Q fragments (tf32, reused by both passes) ----
    uint32_t qa[16][4];
    {
        const float* Qs = VsBuf;
#pragma unroll
        for (int kk = 0; kk < 16; kk++) {
            qa[kk][0] = f2tf(Qs[(r0 + g)     * KSTRIDE + kk * 8 + t]);
            qa[kk][1] = f2tf(Qs[(r0 + g + 8) * KSTRIDE + kk * 8 + t]);
            qa[kk][2] = f2tf(Qs[(r0 + g)     * KSTRIDE + kk * 8 + t + 4]);
            qa[kk][3] = f2tf(Qs[(r0 + g + 8) * KSTRIDE + kk * 8 + t + 4]);
        }
    }
    __syncthreads();

    // ================= PASS 1 : Z1[q] = sum_k exp(-sc * q.k) =================
    load_KV(KsBuf, Kgb, tid);
    cp_commit();
    for (int kt = 0; kt < NKT; kt++) {
        const int cur = kt & 1;
        if (kt + 1 < NKT) {
            load_KV(KsBuf + (cur ^ 1) * SZ_KBUF,
                    Kgb + (size_t)(kt + 1) * TK * Dm, tid);
            cp_commit();
            cp_wait<1>();
        } else {
            cp_wait<0>();
        }
        __syncthreads();

        float s[4][4];
        computeS(s, KsBuf + cur * SZ_KBUF, qa, nw, g, t);

        float z0 = 0.f, z8 = 0.f;
#pragma unroll
        for (int j = 0; j < 4; j++) {
            z0 += __expf(-sc * s[j][0]) + __expf(-sc * s[j][1]);
            z8 += __expf(-sc * s[j][2]) + __expf(-sc * s[j][3]);
        }
        z0 += __shfl_xor_sync(~0u, z0, 1); z0 += __shfl_xor_sync(~0u, z0, 2);
        z8 += __shfl_xor_sync(~0u, z8, 1); z8 += __shfl_xor_sync(~0u, z8, 2);
        if (t == 0) {
            atomicAdd(&Z1[r0 + g],     z0);
            atomicAdd(&Z1[r0 + g + 8], z8);
        }
        __syncthreads();   // guards Ks[cur] against the kt+2 prefetch
    }

    const float rZ1a = 1.f / Z1[r0 + g];
    const float rZ1b = 1.f / Z1[r0 + g + 8];

    // ================= PASS 2 : w = exp(-p*g) ; acc += w*V ; Z2 += w ========
    float acc[8][4];
#pragma unroll
    for (int j = 0; j < 8; j++)
#pragma unroll
        for (int r = 0; r < 4; r++) acc[j][r] = 0.f;
    float z2a = 0.f, z2b = 0.f;

    load_KV(KsBuf, Kgb, tid);
    load_KV(VsBuf, Vgb, tid);
    load_G (GsBuf, Gg0, tid);
    cp_commit();

    for (int kt = 0; kt < NKT; kt++) {
        const int cur = kt & 1;
        if (kt + 1 < NKT) {
            load_KV(KsBuf + (cur ^ 1) * SZ_KBUF,
                    Kgb + (size_t)(kt + 1) * TK * Dm, tid);
            load_KV(VsBuf + (cur ^ 1) * SZ_KBUF,
                    Vgb + (size_t)(kt + 1) * TK * Dm, tid);
            load_G (GsBuf + (cur ^ 1) * SZ_GBUF,
                    Gg0 + (size_t)(kt + 1) * TK, tid);
            cp_commit();
            cp_wait<1>();
        } else {
            cp_wait<0>();
        }
        __syncthreads();

        float s[4][4];
        computeS(s, KsBuf + cur * SZ_KBUF, qa, nw, g, t);

        // w = exp(-p*g), rounded to tf32; stash to smem for the PV mma
        const float* Gs = GsBuf + cur * SZ_GBUF;
#pragma unroll
        for (int j = 0; j < 4; j++) {
            const int cb = nw * 32 + j * 8 + 2 * t;
#pragma unroll
            for (int r2 = 0; r2 < 4; r2++) {
                const int row = (r2 < 2) ? (r0 + g) : (r0 + g + 8);
                const int col = cb + (r2 & 1);
                float p  = __expf(-sc * s[j][r2]) * ((r2 < 2) ? rZ1a : rZ1b);
                float tt = -p * Gs[row * GSTRIDE + col];
                float w  = __expf(tt);
                float wf = __uint_as_float(f2tf(w));
                if (r2 < 2) z2a += wf; else z2b += wf;
                Ws[row * GSTRIDE + col] = wf;
            }
        }
        __syncthreads();   // W visible to all warps

        // acc += W * V
        const float* Vs = VsBuf + cur * SZ_KBUF;
#pragma unroll
        for (int kk = 0; kk < 8; kk++) {
            uint32_t a[4];
            const float* wp = Ws + (r0 + g) * GSTRIDE + kk * 8 + t;
            a[0] = __float_as_uint(wp[0]);
            a[1] = __float_as_uint(wp[8 * GSTRIDE]);
            a[2] = __float_as_uint(wp[4]);
            a[3] = __float_as_uint(wp[8 * GSTRIDE + 4]);
#pragma unroll
            for (int j = 0; j < 8; j++) {
                const float* vp = Vs + (kk * 8 + t) * KSTRIDE + nw * 64 + j * 8 + g;
                uint32_t bb[2] = { f2tf(vp[0]), f2tf(vp[4 * KSTRIDE]) };
                mma8(acc[j], a, bb);
            }
        }
        __syncthreads();   // all warps done with Ws / buffers before next fill
    }

    // ---- Z2 reduce + normalize + store ----
    z2a += __shfl_xor_sync(~0u, z2a, 1); z2a += __shfl_xor_sync(~0u, z2a, 2);
    z2b += __shfl_xor_sync(~0u, z2b, 1); z2b += __shfl_xor_sync(~0u, z2b, 2);
    if (t == 0) {
        atomicAdd(&Z2[r0 + g],     z2a);
        atomicAdd(&Z2[r0 + g + 8], z2b);
    }
    __syncthreads();

    const float rZ2a = 1.f / Z2[r0 + g];
    const float rZ2b = 1.f / Z2[r0 + g + 8];

    float* ob = out + ((size_t)b * LQ + q0) * Dm;
#pragma unroll
    for (int j = 0; j < 8; j++) {
        const int dcol = nw * 64 + j * 8 + 2 * t;
        float2 v0 = make_float2(acc[j][0] * rZ2a, acc[j][1] * rZ2a);
        float2 v1 = make_float2(acc[j][2] * rZ2b, acc[j][3] * rZ2b);
        *(float2*)(ob + (size_t)(r0 + g)     * Dm + dcol) = v0;
        *(float2*)(ob + (size_t)(r0 + g + 8) * Dm + dcol) = v1;
    }
}

// ---------------------------------------------------------------- launch

extern "C" void kernel_launch(void* const* d_in, const int* in_sizes, int n_in,
                              void* d_out, int out_size) {
    // Robust input mapping by element count:
    //   Q,K,V : B*LQ*D = 4,194,304 (in declaration order)
    //   scale : 1
    //   kg_sim: B*LQ*LK = 67,108,864
    const float* qkv[3] = { nullptr, nullptr, nullptr };
    const float* scale = nullptr;
    const float* gsim  = nullptr;
    int nqkv = 0;
    for (int i = 0; i < n_in; i++) {
        if (in_sizes[i] == 1) scale = (const float*)d_in[i];
        else if (in_sizes[i] == Bn * LQ * LK) gsim = (const float*)d_in[i];
        else if (nqkv < 3) qkv[nqkv++] = (const float*)d_in[i];
    }
    const float* Q = qkv[0];
    const float* K = qkv[1];
    const float* V = qkv[2];
    float* out = (float*)d_out;

    cudaFuncSetAttribute(attn_neg_kernel,
                         cudaFuncAttributeMaxDynamicSharedMemorySize,
                         SMEM_BYTES);

    dim3 grid(LQ / TQ, Bn);   // 32 x 16 = 512 CTAs
    attn_neg_kernel<<<grid, THREADS, SMEM_BYTES>>>(Q, K, V, scale, gsim, out);
}

// round 3
// speedup vs baseline: 1.0180x; 1.0180x over previous
#include <cuda_runtime.h>
#include <cstdint>
#include <cstddef>

// Scaled_Dot_Product_Attention_neg : B=16, LQ=LK=2048, D=128 (fp32)
//   s   = -(Q K^T) * scale
//   p   = softmax(s)            (row-wise over k)
//   t   = -p * kg_sim
//   beta= softmax(t)
//   out = beta @ V
//
// Two-pass streaming formulation per (batch, q-tile):
//   pass 1: Z1[q] = sum_k exp(s)        (no max needed: s ~ N(0,1))
//   pass 2: p = exp(s)/Z1 ; w = exp(-p*g) ; Z2 += w ; acc += w*V ; out = acc/Z2
//
// R2 (resubmitted after infra failure): 512 threads (16 warps, 4x4 warp grid)
// for latency hiding; named per-band barrier for the W smem roundtrip instead
// of full __syncthreads.

#define DEV __device__ __forceinline__

static constexpr int Bn  = 16;
static constexpr int LQ  = 2048;
static constexpr int LK  = 2048;
static constexpr int Dm  = 128;

static constexpr int TQ  = 64;
static constexpr int TK  = 64;
static constexpr int NKT = LK / TK;        // 32 k-tiles
static constexpr int THREADS = 512;        // 16 warps: 4 along M x 4 along N/D

static constexpr int KSTRIDE = Dm + 4;     // 132 floats per K/V row (pad)
static constexpr int GSTRIDE = TK + 4;     // 68 floats per G/W row (pad)

// shared memory layout (in floats)
static constexpr int SZ_KBUF = TK * KSTRIDE;            // 8448
static constexpr int SZ_GBUF = TQ * GSTRIDE;            // 4352
static constexpr int OFF_K   = 0;                       // [2][TK][KSTRIDE]
static constexpr int OFF_V   = OFF_K + 2 * SZ_KBUF;     // [2][TK][KSTRIDE]
static constexpr int OFF_G   = OFF_V + 2 * SZ_KBUF;     // [2][TQ][GSTRIDE]
static constexpr int OFF_W   = OFF_G + 2 * SZ_GBUF;     // [TQ][GSTRIDE]
static constexpr int OFF_Z1  = OFF_W + SZ_GBUF;
static constexpr int OFF_Z2  = OFF_Z1 + TQ;
static constexpr int SMEM_FLOATS = OFF_Z2 + TQ;
static constexpr int SMEM_BYTES  = SMEM_FLOATS * 4;     // 187,904 B

// ---------------------------------------------------------------- helpers

DEV uint32_t f2tf(float f) {
    uint32_t r;
    asm("cvt.rna.tf32.f32 %0, %1;" : "=r"(r) : "f"(f));
    return r;
}

DEV void mma8(float* d, const uint32_t* a, const uint32_t* b) {
    asm volatile(
        "mma.sync.aligned.m16n8k8.row.col.f32.tf32.tf32.f32 "
        "{%0,%1,%2,%3}, {%4,%5,%6,%7}, {%8,%9}, {%0,%1,%2,%3};\n"
        : "+f"(d[0]), "+f"(d[1]), "+f"(d[2]), "+f"(d[3])
        : "r"(a[0]), "r"(a[1]), "r"(a[2]), "r"(a[3]),
          "r"(b[0]), "r"(b[1]));
}

DEV void cpa16(float* smem_dst, const float* gmem_src) {
    uint32_t sa = (uint32_t)__cvta_generic_to_shared(smem_dst);
    asm volatile("cp.async.cg.shared.global [%0], [%1], 16;\n"
                 :: "r"(sa), "l"(gmem_src));
}
DEV void cp_commit() { asm volatile("cp.async.commit_group;\n"); }
template <int N> DEV void cp_wait() {
    asm volatile("cp.async.wait_group %0;\n" :: "n"(N));
}

DEV void band_bar(int mw) {   // sync the 4 warps (128 threads) of row-band mw
    asm volatile("bar.sync %0, 128;\n" :: "r"(mw + 1) : "memory");
}

// K/V tile: TK(=64) rows x 128 floats, 2048 float4 / 512 threads = 4 each
DEV void load_KV(float* dst, const float* src_tile, int tid) {
#pragma unroll
    for (int i = 0; i < 4; i++) {
        int idx = i * 512 + tid;
        int row = idx >> 5;
        int c4  = idx & 31;
        cpa16(dst + row * KSTRIDE + c4 * 4,
              src_tile + (size_t)row * Dm + c4 * 4);
    }
}

// G tile: TQ(=64) rows x 64 floats, 1024 float4 / 512 threads = 2 each
DEV void load_G(float* dst, const float* src_tile, int tid) {
#pragma unroll
    for (int i = 0; i < 2; i++) {
        int idx = i * 512 + tid;
        int row = idx >> 4;
        int c4  = idx & 15;
        cpa16(dst + row * GSTRIDE + c4 * 4,
              src_tile + (size_t)row * LK + c4 * 4);
    }
}

// S = Q * K^T for this warp's 16-row x 16-col chunk. qa holds tf32 Q frags.
DEV void computeS(float s[2][4], const float* Ks,
                  const uint32_t (&qa)[16][4], int nw, int g, int t) {
#pragma unroll
    for (int j = 0; j < 2; j++)
#pragma unroll
        for (int r = 0; r < 4; r++) s[j][r] = 0.f;

#pragma unroll
    for (int kk = 0; kk < 16; kk++) {
#pragma unroll
        for (int j = 0; j < 2; j++) {
            const float* kp = Ks + (nw * 16 + j * 8 + g) * KSTRIDE + kk * 8 + t;
            uint32_t bb[2] = { f2tf(kp[0]), f2tf(kp[4]) };
            mma8(s[j], qa[kk], bb);
        }
    }
}

// ---------------------------------------------------------------- kernel

__global__ void __launch_bounds__(THREADS, 1)
attn_neg_kernel(const float* __restrict__ Q, const float* __restrict__ K,
                const float* __restrict__ V, const float* __restrict__ scale_p,
                const float* __restrict__ G, float* __restrict__ out) {
    extern __shared__ float sm[];
    const int tid  = threadIdx.x;
    const int wid  = tid >> 5;
    const int lane = tid & 31;
    const int mw   = wid & 3;      // warp row-band  (0..3) -> rows 16*mw
    const int nw   = wid >> 2;     // warp col-quarter (0..3)
    const int g    = lane >> 2;    // mma groupID
    const int t    = lane & 3;     // mma threadID_in_group

    const int b  = blockIdx.y;
    const int q0 = blockIdx.x * TQ;
    const float sc = *scale_p;

    const float* Qg  = Q + ((size_t)b * LQ + q0) * Dm;
    const float* Kgb = K + (size_t)b * LK * Dm;
    const float* Vgb = V + (size_t)b * LK * Dm;
    const float* Gg0 = G + ((size_t)b * LQ + q0) * (size_t)LK;

    float* KsBuf = sm + OFF_K;
    float* VsBuf = sm + OFF_V;
    float* GsBuf = sm + OFF_G;
    float* Ws    = sm + OFF_W;
    float* Z1    = sm + OFF_Z1;
    float* Z2    = sm + OFF_Z2;

    // ---- stage Q into (currently unused) V buffer, zero Z arrays ----
    {
        float* Qs = VsBuf;
#pragma unroll
        for (int i = 0; i < 4; i++) {
            int idx = i * 512 + tid;
            int row = idx >> 5;
            int c4  = idx & 31;
            float4 v = *(const float4*)(Qg + (size_t)row * Dm + c4 * 4);
            *(float4*)(Qs + row * KSTRIDE + c4 * 4) = v;
        }
        if (tid < TQ) { Z1[tid] = 0.f; Z2[tid] = 0.f; }
    }
    __syncthreads();

    const int r0 = mw * 16;

    // ---- preload Q fragments (tf32, reused by both passes) ----
    uint32_t qa[16][4];
    {
        const float* Qs = VsBuf;
#pragma unroll
        for (int kk = 0; kk < 16; kk++) {
            qa[kk][0] = f2tf(Qs[(r0 + g)     * KSTRIDE + kk * 8 + t]);
            qa[kk][1] = f2tf(Qs[(r0 + g + 8) * KSTRIDE + kk * 8 + t]);
            qa[kk][2] = f2tf(Qs[(r0 + g)     * KSTRIDE + kk * 8 + t + 4]);
            qa[kk][3] = f2tf(Qs[(r0 + g + 8) * KSTRIDE + kk * 8 + t + 4]);
        }
    }
    __syncthreads();

    // ================= PASS 1 : Z1[q] = sum_k exp(-sc * q.k) =================
    load_KV(KsBuf, Kgb, tid);
    cp_commit();
    for (int kt = 0; kt < NKT; kt++) {
        const int cur = kt & 1;
        if (kt + 1 < NKT) {
            load_KV(KsBuf + (cur ^ 1) * SZ_KBUF,
                    Kgb + (size_t)(kt + 1) * TK * Dm, tid);
            cp_commit();
            cp_wait<1>();
        } else {
            cp_wait<0>();
        }
        __syncthreads();

        float s[2][4];
        computeS(s, KsBuf + cur * SZ_KBUF, qa, nw, g, t);

        float z0 = 0.f, z8 = 0.f;
#pragma unroll
        for (int j = 0; j < 2; j++) {
            z0 += __expf(-sc * s[j][0]) + __expf(-sc * s[j][1]);
            z8 += __expf(-sc * s[j][2]) + __expf(-sc * s[j][3]);
        }
        z0 += __shfl_xor_sync(~0u, z0, 1); z0 += __shfl_xor_sync(~0u, z0, 2);
        z8 += __shfl_xor_sync(~0u, z8, 1); z8 += __shfl_xor_sync(~0u, z8, 2);
        if (t == 0) {
            atomicAdd(&Z1[r0 + g],     z0);
            atomicAdd(&Z1[r0 + g + 8], z8);
        }
        __syncthreads();   // guards Ks[cur] against the kt+2 prefetch
    }

    const float rZ1a = 1.f / Z1[r0 + g];
    const float rZ1b = 1.f / Z1[r0 + g + 8];

    // ================= PASS 2 : w = exp(-p*g) ; acc += w*V ; Z2 += w ========
    float acc[4][4];
#pragma unroll
    for (int j = 0; j < 4; j++)
#pragma unroll
        for (int r = 0; r < 4; r++) acc[j][r] = 0.f;
    float z2a = 0.f, z2b = 0.f;

    load_KV(KsBuf, Kgb, tid);
    load_KV(VsBuf, Vgb, tid);
    load_G (GsBuf, Gg0, tid);
    cp_commit();

    for (int kt = 0; kt < NKT; kt++) {
        const int cur = kt & 1;
        if (kt + 1 < NKT) {
            load_KV(KsBuf + (cur ^ 1) * SZ_KBUF,
                    Kgb + (size_t)(kt + 1) * TK * Dm, tid);
            load_KV(VsBuf + (cur ^ 1) * SZ_KBUF,
                    Vgb + (size_t)(kt + 1) * TK * Dm, tid);
            load_G (GsBuf + (cur ^ 1) * SZ_GBUF,
                    Gg0 + (size_t)(kt + 1) * TK, tid);
            cp_commit();
            cp_wait<1>();
        } else {
            cp_wait<0>();
        }
        __syncthreads();

        float s[2][4];
        computeS(s, KsBuf + cur * SZ_KBUF, qa, nw, g, t);

        // w = exp(-p*g), rounded to tf32; stash to smem for the PV mma
        const float* Gs = GsBuf + cur * SZ_GBUF;
#pragma unroll
        for (int j = 0; j < 2; j++) {
            const int cb = nw * 16 + j * 8 + 2 * t;
#pragma unroll
            for (int r2 = 0; r2 < 4; r2++) {
                const int row = (r2 < 2) ? (r0 + g) : (r0 + g + 8);
                const int col = cb + (r2 & 1);
                float p  = __expf(-sc * s[j][r2]) * ((r2 < 2) ? rZ1a : rZ1b);
                float tt = -p * Gs[row * GSTRIDE + col];
                float w  = __expf(tt);
                float wf = __uint_as_float(f2tf(w));
                if (r2 < 2) z2a += wf; else z2b += wf;
                Ws[row * GSTRIDE + col] = wf;
            }
        }
        band_bar(mw);      // W rows of this band visible to the band's 4 warps

        // acc += W * V   (W rows r0..r0+15 only -> band-local dependency)
        const float* Vs = VsBuf + cur * SZ_KBUF;
#pragma unroll
        for (int kk = 0; kk < 8; kk++) {
            uint32_t a[4];
            const float* wp = Ws + (r0 + g) * GSTRIDE + kk * 8 + t;
            a[0] = __float_as_uint(wp[0]);
            a[1] = __float_as_uint(wp[8 * GSTRIDE]);
            a[2] = __float_as_uint(wp[4]);
            a[3] = __float_as_uint(wp[8 * GSTRIDE + 4]);
#pragma unroll
            for (int j = 0; j < 4; j++) {
                const float* vp = Vs + (kk * 8 + t) * KSTRIDE + nw * 32 + j * 8 + g;
                uint32_t bb[2] = { f2tf(vp[0]), f2tf(vp[4 * KSTRIDE]) };
                mma8(acc[j], a, bb);
            }
        }
        __syncthreads();   // all warps done with Ws / buffers before next fill
    }

    // ---- Z2 reduce + normalize + store ----
    z2a += __shfl_xor_sync(~0u, z2a, 1); z2a += __shfl_xor_sync(~0u, z2a, 2);
    z2b += __shfl_xor_sync(~0u, z2b, 1); z2b += __shfl_xor_sync(~0u, z2b, 2);
    if (t == 0) {
        atomicAdd(&Z2[r0 + g],     z2a);
        atomicAdd(&Z2[r0 + g + 8], z2b);
    }
    __syncthreads();

    const float rZ2a = 1.f / Z2[r0 + g];
    const float rZ2b = 1.f / Z2[r0 + g + 8];

    float* ob = out + ((size_t)b * LQ + q0) * Dm;
#pragma unroll
    for (int j = 0; j < 4; j++) {
        const int dcol = nw * 32 + j * 8 + 2 * t;
        float2 v0 = make_float2(acc[j][0] * rZ2a, acc[j][1] * rZ2a);
        float2 v1 = make_float2(acc[j][2] * rZ2b, acc[j][3] * rZ2b);
        *(float2*)(ob + (size_t)(r0 + g)     * Dm + dcol) = v0;
        *(float2*)(ob + (size_t)(r0 + g + 8) * Dm + dcol) = v1;
    }
}

// ---------------------------------------------------------------- launch

extern "C" void kernel_launch(void* const* d_in, const int* in_sizes, int n_in,
                              void* d_out, int out_size) {
    // Robust input mapping by element count:
    //   Q,K,V : B*LQ*D = 4,194,304 (in declaration order)
    //   scale : 1
    //   kg_sim: B*LQ*LK = 67,108,864
    const float* qkv[3] = { nullptr, nullptr, nullptr };
    const float* scale = nullptr;
    const float* gsim  = nullptr;
    int nqkv = 0;
    for (int i = 0; i < n_in; i++) {
        if (in_sizes[i] == 1) scale = (const float*)d_in[i];
        else if (in_sizes[i] == Bn * LQ * LK) gsim = (const float*)d_in[i];
        else if (nqkv < 3) qkv[nqkv++] = (const float*)d_in[i];
    }
    const float* Q = qkv[0];
    const float* K = qkv[1];
    const float* V = qkv[2];
    float* out = (float*)d_out;

    cudaFuncSetAttribute(attn_neg_kernel,
                         cudaFuncAttributeMaxDynamicSharedMemorySize,
                         SMEM_BYTES);

    dim3 grid(LQ / TQ, Bn);   // 32 x 16 = 512 CTAs
    attn_neg_kernel<<<grid, THREADS, SMEM_BYTES>>>(Q, K, V, scale, gsim, out);
}